// round 2
// baseline (speedup 1.0000x reference)
#include <cuda_runtime.h>
#include <math.h>

// Problem geometry (fixed by the dataset)
#define BB 4
#define SS 512
#define DD 4096
#define HH 32
#define HKV 8
#define HD 128
#define STARTP 512
#define TT 1024          // STARTP + SS
#define MTOK (BB*SS)     // 2048

// ---------------- scratch (static device globals; no allocation) -------------
__device__ float g_qlin[(size_t)MTOK * HH * HD];        // 2048 x 4096
__device__ float g_klin[(size_t)MTOK * HKV * HD];       // 2048 x 1024
__device__ float g_vlin[(size_t)MTOK * HKV * HD];       // 2048 x 1024
__device__ float g_kbuf[(size_t)BB * TT * HKV * HD];    // [b,t,kv,hd]
__device__ float g_vbuf[(size_t)BB * TT * HKV * HD];
__device__ float g_scores[(size_t)BB * HH * SS * TT];   // [b,h,s,t]  268 MB
__device__ float g_attn[(size_t)MTOK * HH * HD];        // [b,s,h,hd]

// ---------------- 128x128x8 fp32 tile GEMM core ------------------------------
// C[M,N] = alpha * A[M,K] * op(B);  BT=true: B is [N,K] (NT);  BT=false: B is [K,N] (NN)
// grid: (N/128, M/128, z) ; 256 threads ; each thread 8x8 (split 4+4)
template<bool BT>
__device__ __forceinline__ void gemm_core(
    const float* __restrict__ A, int lda,
    const float* __restrict__ B, int ldb,
    float* __restrict__ C, int ldc,
    int K, float alpha)
{
    __shared__ float As[8][128];
    __shared__ float Bs[8][128];
    const int tid  = threadIdx.x;
    const int bm   = blockIdx.y * 128;
    const int bn   = blockIdx.x * 128;
    const int arow = tid >> 1;          // 0..127
    const int acol = (tid & 1) * 4;     // 0 or 4
    const int nnk  = tid >> 5;          // 0..7   (NN B loader)
    const int nnn  = (tid & 31) * 4;    // 0..124 (NN B loader)
    const int ty   = tid >> 4;          // 0..15
    const int tx   = tid & 15;          // 0..15

    float acc[8][8];
#pragma unroll
    for (int i = 0; i < 8; i++)
#pragma unroll
        for (int j = 0; j < 8; j++) acc[i][j] = 0.0f;

    for (int k0 = 0; k0 < K; k0 += 8) {
        float4 av = *(const float4*)(A + (size_t)(bm + arow) * lda + k0 + acol);
        As[acol + 0][arow] = av.x;
        As[acol + 1][arow] = av.y;
        As[acol + 2][arow] = av.z;
        As[acol + 3][arow] = av.w;
        if (BT) {
            float4 bv = *(const float4*)(B + (size_t)(bn + arow) * ldb + k0 + acol);
            Bs[acol + 0][arow] = bv.x;
            Bs[acol + 1][arow] = bv.y;
            Bs[acol + 2][arow] = bv.z;
            Bs[acol + 3][arow] = bv.w;
        } else {
            float4 bv = *(const float4*)(B + (size_t)(k0 + nnk) * ldb + bn + nnn);
            *(float4*)&Bs[nnk][nnn] = bv;
        }
        __syncthreads();
#pragma unroll
        for (int kk = 0; kk < 8; kk++) {
            float4 a0 = *(const float4*)&As[kk][ty * 4];
            float4 a1 = *(const float4*)&As[kk][64 + ty * 4];
            float4 b0 = *(const float4*)&Bs[kk][tx * 4];
            float4 b1 = *(const float4*)&Bs[kk][64 + tx * 4];
            float ar[8] = {a0.x, a0.y, a0.z, a0.w, a1.x, a1.y, a1.z, a1.w};
            float br[8] = {b0.x, b0.y, b0.z, b0.w, b1.x, b1.y, b1.z, b1.w};
#pragma unroll
            for (int i = 0; i < 8; i++)
#pragma unroll
                for (int j = 0; j < 8; j++)
                    acc[i][j] = fmaf(ar[i], br[j], acc[i][j]);
        }
        __syncthreads();
    }

#pragma unroll
    for (int qi = 0; qi < 2; qi++) {
#pragma unroll
        for (int i = 0; i < 4; i++) {
            int r = bm + qi * 64 + ty * 4 + i;
#pragma unroll
            for (int qj = 0; qj < 2; qj++) {
                float4 v;
                v.x = alpha * acc[qi * 4 + i][qj * 4 + 0];
                v.y = alpha * acc[qi * 4 + i][qj * 4 + 1];
                v.z = alpha * acc[qi * 4 + i][qj * 4 + 2];
                v.w = alpha * acc[qi * 4 + i][qj * 4 + 3];
                *(float4*)(C + (size_t)r * ldc + bn + qj * 64 + tx * 4) = v;
            }
        }
    }
}

__global__ __launch_bounds__(256) void gemm_nt_kernel(
    int K, const float* __restrict__ A, int lda,
    const float* __restrict__ B, int ldb,
    float* __restrict__ C, int ldc, float alpha)
{
    gemm_core<true>(A, lda, B, ldb, C, ldc, K, alpha);
}

// scores[b,h,s,t] = (1/sqrt(HD)) * dot(q[b,s,h,:], k[b,t,h/4,:])
__global__ __launch_bounds__(256) void scores_kernel()
{
    int z = blockIdx.z;           // b*32 + h
    int b = z >> 5, h = z & 31, kv = h >> 2;
    const float* A  = g_qlin + (size_t)b * SS * HH * HD + (size_t)h * HD;
    const float* Bp = g_kbuf + (size_t)b * TT * HKV * HD + (size_t)kv * HD;
    float*       C  = g_scores + (size_t)z * SS * TT;
    gemm_core<true>(A, HH * HD, Bp, HKV * HD, C, TT, HD, 0.08838834764831843f);
}

// attn[b,s,h,hd] = sum_t probs[b,h,s,t] * v[b,t,h/4,hd]
__global__ __launch_bounds__(256) void pv_kernel()
{
    int z = blockIdx.z;
    int b = z >> 5, h = z & 31, kv = h >> 2;
    const float* A  = g_scores + (size_t)z * SS * TT;
    const float* Bp = g_vbuf + (size_t)b * TT * HKV * HD + (size_t)kv * HD;
    float*       C  = g_attn + (size_t)b * SS * HH * HD + (size_t)h * HD;
    gemm_core<false>(A, TT, Bp, HKV * HD, C, HH * HD, TT, 1.0f);
}

// ---------------- RoPE + scatter ---------------------------------------------
__global__ void rope_q_kernel(const float* __restrict__ fc, const float* __restrict__ fs)
{
    int idx = blockIdx.x * blockDim.x + threadIdx.x;   // BB*SS*HH*64 pairs
    int p = idx & 63; int rest = idx >> 6;
    int h = rest & 31; rest >>= 5;
    int s = rest & 511; int b = rest >> 9;
    float c  = fc[s * 64 + p];
    float si = fs[s * 64 + p];
    float* ptr = g_qlin + (((size_t)(b * SS + s) * HH + h) * HD + 2 * p);
    float a = ptr[0], bb = ptr[1];
    ptr[0] = a * c - bb * si;
    ptr[1] = a * si + bb * c;
}

__global__ void rope_k_kernel(const float* __restrict__ fc, const float* __restrict__ fs)
{
    int idx = blockIdx.x * blockDim.x + threadIdx.x;   // BB*SS*HKV*64 pairs
    int p = idx & 63; int rest = idx >> 6;
    int kv = rest & 7; rest >>= 3;
    int s = rest & 511; int b = rest >> 9;
    float c  = fc[s * 64 + p];
    float si = fs[s * 64 + p];
    const float* src = g_klin + (((size_t)(b * SS + s) * HKV + kv) * HD + 2 * p);
    float* dst = g_kbuf + (((size_t)(b * TT + STARTP + s) * HKV + kv) * HD + 2 * p);
    float a = src[0], bb = src[1];
    dst[0] = a * c - bb * si;
    dst[1] = a * si + bb * c;
}

// cache_k -> kbuf[:, :512], cache_v -> vbuf[:, :512], vlin -> vbuf[:, 512:]
__global__ void scatter_cache_kernel(const float* __restrict__ ck, const float* __restrict__ cv)
{
    int idx = blockIdx.x * blockDim.x + threadIdx.x;   // 3 * BB*SS*HKV*HD
    int seg = idx >> 21;                               // /2097152
    int i   = idx & ((1 << 21) - 1);
    int b   = i >> 19;                                 // /524288
    int w   = i & ((1 << 19) - 1);
    if (seg == 0)      g_kbuf[(size_t)b * (TT * HKV * HD) + w] = ck[i];
    else if (seg == 1) g_vbuf[(size_t)b * (TT * HKV * HD) + w] = cv[i];
    else               g_vbuf[(size_t)b * (TT * HKV * HD) + (SS * HKV * HD) + w] = g_vlin[i];
}

// ---------------- masked softmax over rows of g_scores -----------------------
__global__ __launch_bounds__(128) void softmax_kernel()
{
    int r = blockIdx.x;          // (b*H + h)*S + s  -> 65536 rows
    int s = r & 511;
    int L = STARTP + 1 + s;      // valid keys: t <= 512+s
    float* row = g_scores + (size_t)r * TT;
    int tid = threadIdx.x;
    int lane = tid & 31, warp = tid >> 5;
    __shared__ float red[4];

    float v[8];
    float m = -INFINITY;
#pragma unroll
    for (int j = 0; j < 8; j++) {
        int t = j * 128 + tid;
        float x = (t < L) ? row[t] : -INFINITY;
        v[j] = x;
        m = fmaxf(m, x);
    }
#pragma unroll
    for (int o = 16; o > 0; o >>= 1) m = fmaxf(m, __shfl_xor_sync(0xffffffffu, m, o));
    if (lane == 0) red[warp] = m;
    __syncthreads();
    m = fmaxf(fmaxf(red[0], red[1]), fmaxf(red[2], red[3]));
    __syncthreads();

    float sum = 0.0f;
#pragma unroll
    for (int j = 0; j < 8; j++) {
        float e = expf(v[j] - m);     // masked: exp(-inf) = 0
        v[j] = e;
        sum += e;
    }
#pragma unroll
    for (int o = 16; o > 0; o >>= 1) sum += __shfl_xor_sync(0xffffffffu, sum, o);
    if (lane == 0) red[warp] = sum;
    __syncthreads();
    sum = red[0] + red[1] + red[2] + red[3];
    float inv = 1.0f / sum;
#pragma unroll
    for (int j = 0; j < 8; j++) {
        int t = j * 128 + tid;
        row[t] = v[j] * inv;
    }
}

// ---------------- launch -----------------------------------------------------
extern "C" void kernel_launch(void* const* d_in, const int* in_sizes, int n_in,
                              void* d_out, int out_size)
{
    const float* x  = (const float*)d_in[0];
    const float* wq = (const float*)d_in[1];
    const float* wk = (const float*)d_in[2];
    const float* wv = (const float*)d_in[3];
    const float* wo = (const float*)d_in[4];
    const float* fc = (const float*)d_in[5];
    const float* fs = (const float*)d_in[6];
    const float* ck = (const float*)d_in[7];
    const float* cv = (const float*)d_in[8];
    float* out = (float*)d_out;

    float *qlin, *klin, *vlin, *attn;
    cudaGetSymbolAddress((void**)&qlin, g_qlin);
    cudaGetSymbolAddress((void**)&klin, g_klin);
    cudaGetSymbolAddress((void**)&vlin, g_vlin);
    cudaGetSymbolAddress((void**)&attn, g_attn);

    // 1) Q/K/V projections (NT: W is [N,K])
    gemm_nt_kernel<<<dim3(32, 16, 1), 256>>>(DD, x, DD, wq, DD, qlin, HH * HD, 1.0f);
    gemm_nt_kernel<<<dim3(8, 16, 1), 256>>>(DD, x, DD, wk, DD, klin, HKV * HD, 1.0f);
    gemm_nt_kernel<<<dim3(8, 16, 1), 256>>>(DD, x, DD, wv, DD, vlin, HKV * HD, 1.0f);

    // 2) RoPE (q in place, k -> kbuf), cache concat + v scatter
    rope_q_kernel<<<(BB * SS * HH * 64) / 256, 256>>>(fc, fs);
    rope_k_kernel<<<(BB * SS * HKV * 64) / 256, 256>>>(fc, fs);
    scatter_cache_kernel<<<(3 * BB * SS * HKV * HD) / 256, 256>>>(ck, cv);

    // 3) scores = scale * Q K^T  (batched over b,h)
    scores_kernel<<<dim3(TT / 128, SS / 128, BB * HH), 256>>>();

    // 4) causal softmax
    softmax_kernel<<<BB * HH * SS, 128>>>();

    // 5) attn = P V  (batched, NN)
    pv_kernel<<<dim3(HD / 128, SS / 128, BB * HH), 256>>>();

    // 6) output projection -> d_out
    gemm_nt_kernel<<<dim3(32, 16, 1), 256>>>(HH * HD, attn, HH * HD, wo, HH * HD, out, DD, 1.0f);
}

// round 4
// speedup vs baseline: 2.3931x; 2.3931x over previous
#include <cuda_runtime.h>
#include <cuda_fp16.h>
#include <math.h>
#include <stdint.h>

#define BB 4
#define SS 512
#define DD 4096
#define HH 32
#define HKV 8
#define HD 128
#define STARTP 512
#define TT 1024
#define MTOK (BB*SS)

// ---------------- scratch (static device globals) ----------------------------
__device__ float g_qlin[(size_t)MTOK * DD];
__device__ float g_klin[(size_t)MTOK * HKV * HD];
__device__ float g_vlin[(size_t)MTOK * HKV * HD];
__device__ float g_scores[(size_t)BB * HH * SS * TT];

__device__ __half g_xhi[(size_t)MTOK * DD],  g_xlo[(size_t)MTOK * DD];
__device__ __half g_wqhi[(size_t)DD * DD],   g_wqlo[(size_t)DD * DD];
__device__ __half g_wkhi[(size_t)HKV*HD*DD], g_wklo[(size_t)HKV*HD*DD];
__device__ __half g_wvhi[(size_t)HKV*HD*DD], g_wvlo[(size_t)HKV*HD*DD];
__device__ __half g_wohi[(size_t)DD * DD],   g_wolo[(size_t)DD * DD];
__device__ __half g_qhi[(size_t)MTOK * DD],  g_qlo[(size_t)MTOK * DD];
__device__ __half g_khi[(size_t)BB*TT*HKV*HD], g_klo[(size_t)BB*TT*HKV*HD];
__device__ __half g_vThi[(size_t)BB*HKV*HD*TT], g_vTlo[(size_t)BB*HKV*HD*TT];
__device__ __half g_phi[(size_t)BB*HH*SS*TT], g_plo[(size_t)BB*HH*SS*TT];
__device__ __half g_ahi[(size_t)MTOK * DD],  g_alo[(size_t)MTOK * DD];

// ---------------- PTX helpers ------------------------------------------------
__device__ __forceinline__ uint32_t smem_u32(const void* p){
    uint32_t a;
    asm("{ .reg .u64 t; cvta.to.shared.u64 t, %1; cvt.u32.u64 %0, t; }" : "=r"(a) : "l"(p));
    return a;
}
__device__ __forceinline__ void cpasync16(uint32_t d, const void* g){
    asm volatile("cp.async.cg.shared.global [%0], [%1], 16;" :: "r"(d), "l"(g));
}
__device__ __forceinline__ void ldsm4(uint32_t* x, uint32_t a){
    asm volatile("ldmatrix.sync.aligned.m8n8.x4.shared.b16 {%0,%1,%2,%3}, [%4];"
        : "=r"(x[0]), "=r"(x[1]), "=r"(x[2]), "=r"(x[3]) : "r"(a));
}
__device__ __forceinline__ void mma16816(float* d, const uint32_t* a, uint32_t b0, uint32_t b1){
    asm volatile("mma.sync.aligned.m16n8k16.row.col.f32.f16.f16.f32 "
        "{%0,%1,%2,%3}, {%4,%5,%6,%7}, {%8,%9}, {%0,%1,%2,%3};"
        : "+f"(d[0]), "+f"(d[1]), "+f"(d[2]), "+f"(d[3])
        : "r"(a[0]), "r"(a[1]), "r"(a[2]), "r"(a[3]), "r"(b0), "r"(b1));
}

// smem layout (halves): per buffer  Ah@0  Al@5120  Bh@10240  Bl@15360 (pitch 40)
// buffer stride 20480 halves (40960 B); two buffers -> 81920 B
#define PITCH 40
#define ABYTES 10240
#define BUFBYTES 40960
#define DSMEM 81920

// ---------------- split-f16 HMMA GEMM core -----------------------------------
// C[M,N] = alpha * A * B^T ;  A[M,K] hi/lo (lda), B[N,K] hi/lo (ldb)
// A*B ~= Ah*Bh + Ah*Bl + Al*Bh
// EPI=0: fp32 store to C.  EPI=1: split-f16 store to Chi/Clo.
template<int EPI>
__device__ __forceinline__ void mma_core(
    const __half* __restrict__ Ahi, const __half* __restrict__ Alo, int lda,
    const __half* __restrict__ Bhi, const __half* __restrict__ Blo, int ldb,
    float* __restrict__ C, __half* __restrict__ Chi, __half* __restrict__ Clo, int ldc,
    int K, float alpha)
{
    extern __shared__ __half sm[];
    const uint32_t sbase = smem_u32(sm);
    const int tid  = threadIdx.x;
    const int lane = tid & 31, wid = tid >> 5;
    const int wm = (wid & 3) * 32;      // warp M offset in tile
    const int wn = (wid >> 2) * 64;     // warp N offset in tile
    const int bm = blockIdx.y * 128, bn = blockIdx.x * 128;

    float acc[2][8][4];
#pragma unroll
    for (int i = 0; i < 2; i++)
#pragma unroll
        for (int j = 0; j < 8; j++)
#pragma unroll
            for (int k = 0; k < 4; k++) acc[i][j][k] = 0.0f;

    // ldmatrix per-thread offsets (bytes)
    const int q = lane >> 3, r = lane & 7;
    const uint32_t offA = (uint32_t)(((wm + (q & 1) * 8 + r) * PITCH + (q >> 1) * 8) * 2);
    const uint32_t offB = (uint32_t)(((wn + (q >> 1) * 8 + r) * PITCH + (q & 1) * 8) * 2);

    // cp.async task mapping: ids tid and tid+256; row=id>>2, seg=id&3
    const int row0 = tid >> 2, seg0 = (tid & 3) * 8;
    const int row1 = (tid + 256) >> 2, seg1 = ((tid + 256) & 3) * 8;

    const int NC = K >> 5;

#define LOAD_CHUNK(c, buf) do {                                                  \
    uint32_t db = sbase + (buf) * BUFBYTES;                                      \
    const __half* a0 = Ahi + (size_t)(bm + row0) * lda + (c) * 32 + seg0;        \
    const __half* l0 = Alo + (size_t)(bm + row0) * lda + (c) * 32 + seg0;        \
    const __half* b0 = Bhi + (size_t)(bn + row0) * ldb + (c) * 32 + seg0;        \
    const __half* c0 = Blo + (size_t)(bn + row0) * ldb + (c) * 32 + seg0;        \
    uint32_t d0 = db + (uint32_t)(row0 * PITCH + seg0) * 2;                      \
    cpasync16(d0, a0);  cpasync16(d0 + ABYTES, l0);                              \
    cpasync16(d0 + 2*ABYTES, b0);  cpasync16(d0 + 3*ABYTES, c0);                 \
    const __half* a1 = Ahi + (size_t)(bm + row1) * lda + (c) * 32 + seg1;        \
    const __half* l1 = Alo + (size_t)(bm + row1) * lda + (c) * 32 + seg1;        \
    const __half* b1 = Bhi + (size_t)(bn + row1) * ldb + (c) * 32 + seg1;        \
    const __half* c1 = Blo + (size_t)(bn + row1) * ldb + (c) * 32 + seg1;        \
    uint32_t d1 = db + (uint32_t)(row1 * PITCH + seg1) * 2;                      \
    cpasync16(d1, a1);  cpasync16(d1 + ABYTES, l1);                              \
    cpasync16(d1 + 2*ABYTES, b1);  cpasync16(d1 + 3*ABYTES, c1);                 \
    asm volatile("cp.async.commit_group;" ::: "memory");                         \
} while (0)

    LOAD_CHUNK(0, 0);

    for (int c = 0; c < NC; ++c) {
        if (c + 1 < NC) {
            LOAD_CHUNK(c + 1, (c + 1) & 1);
            asm volatile("cp.async.wait_group 1;" ::: "memory");
        } else {
            asm volatile("cp.async.wait_group 0;" ::: "memory");
        }
        __syncthreads();

        uint32_t base = sbase + (c & 1) * BUFBYTES;
#pragma unroll
        for (int ks = 0; ks < 2; ks++) {
            uint32_t ah[2][4], al[2][4], bh[4][4], bl[4][4];
            const uint32_t kso = (uint32_t)(ks * 16 * 2);
#pragma unroll
            for (int mt = 0; mt < 2; mt++) {
                uint32_t o = base + offA + (uint32_t)(mt * 16 * PITCH * 2) + kso;
                ldsm4(ah[mt], o);
                ldsm4(al[mt], o + ABYTES);
            }
#pragma unroll
            for (int j = 0; j < 4; j++) {
                uint32_t o = base + 2 * ABYTES + offB + (uint32_t)(j * 16 * PITCH * 2) + kso;
                ldsm4(bh[j], o);
                ldsm4(bl[j], o + ABYTES);
            }
#pragma unroll
            for (int mt = 0; mt < 2; mt++)
#pragma unroll
                for (int nt = 0; nt < 8; nt++) {
                    const int j = nt >> 1, o = (nt & 1) * 2;
                    mma16816(acc[mt][nt], ah[mt], bh[j][o], bh[j][o + 1]);
                    mma16816(acc[mt][nt], ah[mt], bl[j][o], bl[j][o + 1]);
                    mma16816(acc[mt][nt], al[mt], bh[j][o], bh[j][o + 1]);
                }
        }
        __syncthreads();
    }
#undef LOAD_CHUNK

    // epilogue
    const int er = bm + wm + (lane >> 2);
    const int ec = bn + wn + 2 * (lane & 3);
#pragma unroll
    for (int mt = 0; mt < 2; mt++)
#pragma unroll
        for (int nt = 0; nt < 8; nt++) {
            int rr = er + mt * 16;
            int cc = ec + nt * 8;
            float v0 = alpha * acc[mt][nt][0];
            float v1 = alpha * acc[mt][nt][1];
            float v2 = alpha * acc[mt][nt][2];
            float v3 = alpha * acc[mt][nt][3];
            if (EPI == 0) {
                *(float2*)(C + (size_t)rr * ldc + cc)       = make_float2(v0, v1);
                *(float2*)(C + (size_t)(rr + 8) * ldc + cc) = make_float2(v2, v3);
            } else {
                __half h0 = __float2half_rn(v0), h1 = __float2half_rn(v1);
                __half h2 = __float2half_rn(v2), h3 = __float2half_rn(v3);
                *(__half2*)(Chi + (size_t)rr * ldc + cc) = __halves2half2(h0, h1);
                *(__half2*)(Clo + (size_t)rr * ldc + cc) = __halves2half2(
                    __float2half_rn(v0 - __half2float(h0)), __float2half_rn(v1 - __half2float(h1)));
                *(__half2*)(Chi + (size_t)(rr + 8) * ldc + cc) = __halves2half2(h2, h3);
                *(__half2*)(Clo + (size_t)(rr + 8) * ldc + cc) = __halves2half2(
                    __float2half_rn(v2 - __half2float(h2)), __float2half_rn(v3 - __half2float(h3)));
            }
        }
}

__global__ __launch_bounds__(256, 1) void tc_gemm_f32(
    const __half* Ahi, const __half* Alo, int lda,
    const __half* Bhi, const __half* Blo, int ldb,
    float* C, int ldc, int K, float alpha)
{
    mma_core<0>(Ahi, Alo, lda, Bhi, Blo, ldb, C, nullptr, nullptr, ldc, K, alpha);
}

__global__ __launch_bounds__(256, 1) void tc_scores()
{
    int z = blockIdx.z; int b = z >> 5, h = z & 31, kv = h >> 2;
    size_t ao = (size_t)b * SS * DD + (size_t)h * HD;
    size_t bo = ((size_t)b * TT * HKV + kv) * HD;
    mma_core<0>(g_qhi + ao, g_qlo + ao, DD, g_khi + bo, g_klo + bo, HKV * HD,
                g_scores + (size_t)z * SS * TT, nullptr, nullptr, TT, HD, 0.08838834764831843f);
}

__global__ __launch_bounds__(256, 1) void tc_pv()
{
    int z = blockIdx.z; int b = z >> 5, h = z & 31, kv = h >> 2;
    size_t ao = (size_t)z * SS * TT;
    size_t bo = ((size_t)(b * HKV + kv) * HD) * TT;
    size_t co = ((size_t)b * SS * HH + h) * HD;
    mma_core<1>(g_phi + ao, g_plo + ao, TT, g_vThi + bo, g_vTlo + bo, TT,
                nullptr, g_ahi + co, g_alo + co, DD, TT, 1.0f);
}

// ---------------- elementwise / setup ----------------------------------------
__global__ void split2h(const float* __restrict__ src, __half* __restrict__ hi,
                        __half* __restrict__ lo, int n)
{
    for (int i = blockIdx.x * blockDim.x + threadIdx.x; i < n; i += gridDim.x * blockDim.x) {
        float v = src[i];
        __half h = __float2half_rn(v);
        hi[i] = h;
        lo[i] = __float2half_rn(v - __half2float(h));
    }
}

__global__ void rope_q_kernel(const float* __restrict__ fc, const float* __restrict__ fs)
{
    int idx = blockIdx.x * blockDim.x + threadIdx.x;    // BB*SS*HH*64 pairs
    int p = idx & 63; int rest = idx >> 6;
    int h = rest & 31; rest >>= 5;
    int s = rest & 511; int b = rest >> 9;
    float c  = fc[s * 64 + p];
    float si = fs[s * 64 + p];
    size_t o = ((size_t)(b * SS + s) * HH + h) * HD + 2 * p;
    float a = g_qlin[o], bb = g_qlin[o + 1];
    float o0 = a * c - bb * si, o1 = a * si + bb * c;
    __half h0 = __float2half_rn(o0), h1 = __float2half_rn(o1);
    g_qhi[o] = h0;     g_qlo[o]     = __float2half_rn(o0 - __half2float(h0));
    g_qhi[o + 1] = h1; g_qlo[o + 1] = __float2half_rn(o1 - __half2float(h1));
}

__global__ void rope_k_kernel(const float* __restrict__ fc, const float* __restrict__ fs)
{
    int idx = blockIdx.x * blockDim.x + threadIdx.x;    // BB*SS*HKV*64 pairs
    int p = idx & 63; int rest = idx >> 6;
    int kv = rest & 7; rest >>= 3;
    int s = rest & 511; int b = rest >> 9;
    float c  = fc[s * 64 + p];
    float si = fs[s * 64 + p];
    size_t so = ((size_t)(b * SS + s) * HKV + kv) * HD + 2 * p;
    size_t dd = ((size_t)(b * TT + STARTP + s) * HKV + kv) * HD + 2 * p;
    float a = g_klin[so], bb = g_klin[so + 1];
    float o0 = a * c - bb * si, o1 = a * si + bb * c;
    __half h0 = __float2half_rn(o0), h1 = __float2half_rn(o1);
    g_khi[dd] = h0;     g_klo[dd]     = __float2half_rn(o0 - __half2float(h0));
    g_khi[dd + 1] = h1; g_klo[dd + 1] = __float2half_rn(o1 - __half2float(h1));
}

__global__ void cachek_kernel(const float* __restrict__ ck)
{
    int i = blockIdx.x * blockDim.x + threadIdx.x;      // BB*STARTP*HKV*HD
    int b = i >> 19;
    size_t d = (size_t)i + (size_t)b * (STARTP * HKV * HD);
    float v = ck[i];
    __half h = __float2half_rn(v);
    g_khi[d] = h;
    g_klo[d] = __float2half_rn(v - __half2float(h));
}

// V^T build: vT[b][kv][hd][t] from cache_v (t<512) and g_vlin (t>=512), split f16
__global__ void vT_build(const float* __restrict__ cv)
{
    int bkv = blockIdx.z; int b = bkv >> 3, kv = bkv & 7;
    int t0 = blockIdx.x * 32, hd0 = blockIdx.y * 32;
    __shared__ float tile[32][33];
    for (int i = threadIdx.y; i < 32; i += 8) {
        int t = t0 + i; int hd = hd0 + threadIdx.x;
        float v;
        if (t < STARTP) v = cv[(((size_t)b * STARTP + t) * HKV + kv) * HD + hd];
        else            v = g_vlin[(((size_t)b * SS + (t - STARTP)) * HKV + kv) * HD + hd];
        tile[i][threadIdx.x] = v;
    }
    __syncthreads();
    for (int i = threadIdx.y; i < 32; i += 8) {
        int hd = hd0 + i; int t = t0 + threadIdx.x;
        float v = tile[threadIdx.x][i];
        __half h = __float2half_rn(v);
        size_t o = ((size_t)bkv * HD + hd) * TT + t;
        g_vThi[o] = h;
        g_vTlo[o] = __float2half_rn(v - __half2float(h));
    }
}

__global__ __launch_bounds__(128) void softmax_kernel()
{
    int rI = blockIdx.x;             // (b*H+h)*S + s
    int s = rI & 511;
    int L = STARTP + 1 + s;
    const float* row = g_scores + (size_t)rI * TT;
    int tid = threadIdx.x;
    int lane = tid & 31, warp = tid >> 5;
    __shared__ float red[4];

    float v[8];
    float m = -INFINITY;
#pragma unroll
    for (int j = 0; j < 8; j++) {
        int t = j * 128 + tid;
        float x = (t < L) ? row[t] : -INFINITY;
        v[j] = x;
        m = fmaxf(m, x);
    }
#pragma unroll
    for (int o = 16; o > 0; o >>= 1) m = fmaxf(m, __shfl_xor_sync(0xffffffffu, m, o));
    if (lane == 0) red[warp] = m;
    __syncthreads();
    m = fmaxf(fmaxf(red[0], red[1]), fmaxf(red[2], red[3]));
    __syncthreads();

    float sum = 0.0f;
#pragma unroll
    for (int j = 0; j < 8; j++) {
        float e = expf(v[j] - m);
        v[j] = e;
        sum += e;
    }
#pragma unroll
    for (int o = 16; o > 0; o >>= 1) sum += __shfl_xor_sync(0xffffffffu, sum, o);
    if (lane == 0) red[warp] = sum;
    __syncthreads();
    sum = red[0] + red[1] + red[2] + red[3];
    float inv = 1.0f / sum;
#pragma unroll
    for (int j = 0; j < 8; j++) {
        int t = j * 128 + tid;
        float p = v[j] * inv;
        __half h = __float2half_rn(p);
        g_phi[(size_t)rI * TT + t] = h;
        g_plo[(size_t)rI * TT + t] = __float2half_rn(p - __half2float(h));
    }
}

// ---------------- launch -----------------------------------------------------
extern "C" void kernel_launch(void* const* d_in, const int* in_sizes, int n_in,
                              void* d_out, int out_size)
{
    const float* x  = (const float*)d_in[0];
    const float* wq = (const float*)d_in[1];
    const float* wk = (const float*)d_in[2];
    const float* wv = (const float*)d_in[3];
    const float* wo = (const float*)d_in[4];
    const float* fc = (const float*)d_in[5];
    const float* fs = (const float*)d_in[6];
    const float* ck = (const float*)d_in[7];
    const float* cv = (const float*)d_in[8];
    float* out = (float*)d_out;

    cudaFuncSetAttribute(tc_gemm_f32, cudaFuncAttributeMaxDynamicSharedMemorySize, DSMEM);
    cudaFuncSetAttribute(tc_scores,  cudaFuncAttributeMaxDynamicSharedMemorySize, DSMEM);
    cudaFuncSetAttribute(tc_pv,      cudaFuncAttributeMaxDynamicSharedMemorySize, DSMEM);

    __half *xhi,*xlo,*wqhi,*wqlo,*wkhi,*wklo,*wvhi,*wvlo,*wohi,*wolo,*ahi,*alo;
    float *qlin,*klin,*vlin;
    cudaGetSymbolAddress((void**)&xhi, g_xhi);   cudaGetSymbolAddress((void**)&xlo, g_xlo);
    cudaGetSymbolAddress((void**)&wqhi, g_wqhi); cudaGetSymbolAddress((void**)&wqlo, g_wqlo);
    cudaGetSymbolAddress((void**)&wkhi, g_wkhi); cudaGetSymbolAddress((void**)&wklo, g_wklo);
    cudaGetSymbolAddress((void**)&wvhi, g_wvhi); cudaGetSymbolAddress((void**)&wvlo, g_wvlo);
    cudaGetSymbolAddress((void**)&wohi, g_wohi); cudaGetSymbolAddress((void**)&wolo, g_wolo);
    cudaGetSymbolAddress((void**)&ahi, g_ahi);   cudaGetSymbolAddress((void**)&alo, g_alo);
    cudaGetSymbolAddress((void**)&qlin, g_qlin);
    cudaGetSymbolAddress((void**)&klin, g_klin);
    cudaGetSymbolAddress((void**)&vlin, g_vlin);

    // 0) split inputs to f16 hi/lo
    split2h<<<4096, 256>>>(x,  xhi,  xlo,  MTOK * DD);
    split2h<<<4096, 256>>>(wq, wqhi, wqlo, DD * DD);
    split2h<<<4096, 256>>>(wk, wkhi, wklo, HKV * HD * DD);
    split2h<<<4096, 256>>>(wv, wvhi, wvlo, HKV * HD * DD);
    split2h<<<4096, 256>>>(wo, wohi, wolo, DD * DD);

    // 1) projections (HMMA, fp32 out)
    tc_gemm_f32<<<dim3(32, 16), 256, DSMEM>>>(xhi, xlo, DD, wqhi, wqlo, DD, qlin, DD, DD, 1.0f);
    tc_gemm_f32<<<dim3(8, 16), 256, DSMEM>>>(xhi, xlo, DD, wkhi, wklo, DD, klin, HKV * HD, DD, 1.0f);
    tc_gemm_f32<<<dim3(8, 16), 256, DSMEM>>>(xhi, xlo, DD, wvhi, wvlo, DD, vlin, HKV * HD, DD, 1.0f);

    // 2) rope + KV assembly (split f16)
    rope_q_kernel<<<(BB * SS * HH * 64) / 256, 256>>>(fc, fs);
    rope_k_kernel<<<(BB * SS * HKV * 64) / 256, 256>>>(fc, fs);
    cachek_kernel<<<(BB * STARTP * HKV * HD) / 256, 256>>>(ck);
    vT_build<<<dim3(TT / 32, HD / 32, BB * HKV), dim3(32, 8)>>>(cv);

    // 3) scores = scale * Q K^T
    tc_scores<<<dim3(TT / 128, SS / 128, BB * HH), 256, DSMEM>>>();

    // 4) causal softmax -> split-f16 probs
    softmax_kernel<<<BB * HH * SS, 128>>>();

    // 5) attn = P V  -> split-f16
    tc_pv<<<dim3(1, SS / 128, BB * HH), 256, DSMEM>>>();

    // 6) output projection -> d_out (fp32)
    tc_gemm_f32<<<dim3(32, 16), 256, DSMEM>>>(ahi, alo, DD, wohi, wolo, DD, out, DD, DD, 1.0f);
}